// round 14
// baseline (speedup 1.0000x reference)
#include <cuda_runtime.h>
#include <cuda_fp16.h>
#include <cstdint>

#define B_ 1024
#define N_ 128
#define H_ 128
#define D_ 8
#define NT 9   // 8 g col-tiles (128 cols) + 1 f tile

// Packed X operand (prep_x writes, main reads)
// g_xa: [mtile 8][chunk 8][m 128][k16] fp16 pairs (single-level X)
__device__ __align__(16) unsigned g_xa[8 * 8 * 128 * 8];           // 256KB

// ---------------- helpers ----------------
__device__ __forceinline__ uint32_t smem_u32(const void* p) {
    uint32_t a;
    asm("{ .reg .u64 t; cvta.to.shared.u64 t, %1; cvt.u32.u64 %0, t; }" : "=r"(a) : "l"(p));
    return a;
}
__device__ __forceinline__ unsigned pack_h2(__half a, __half b) {
    __half2 t = __halves2half2(a, b);
    return *reinterpret_cast<unsigned*>(&t);
}
__device__ __forceinline__ float elu1(float x) {
    return x > 0.0f ? x : (__expf(x) - 1.0f);
}

#define CP16(s, g) asm volatile("cp.async.cg.shared.global [%0], [%1], 16;" :: "r"(s), "l"(g))
#define CP_COMMIT() asm volatile("cp.async.commit_group;" ::: "memory")
#define CP_WAIT(n)  asm volatile("cp.async.wait_group %0;" :: "n"(n) : "memory")

#define LDM4(r0, r1, r2, r3, a) \
    asm volatile("ldmatrix.sync.aligned.m8n8.x4.shared.b16 {%0,%1,%2,%3}, [%4];" \
        : "=r"(r0), "=r"(r1), "=r"(r2), "=r"(r3) : "r"(a))

#define LDM4T(r0, r1, r2, r3, a) \
    asm volatile("ldmatrix.sync.aligned.m8n8.x4.trans.shared.b16 {%0,%1,%2,%3}, [%4];" \
        : "=r"(r0), "=r"(r1), "=r"(r2), "=r"(r3) : "r"(a))

#define MMA16816(c, a, b) \
    asm volatile("mma.sync.aligned.m16n8k16.row.col.f32.f16.f16.f32 " \
        "{%0,%1,%2,%3}, {%4,%5,%6,%7}, {%8,%9}, {%0,%1,%2,%3};" \
        : "+f"((c)[0]), "+f"((c)[1]), "+f"((c)[2]), "+f"((c)[3]) \
        : "r"((a)[0]), "r"((a)[1]), "r"((a)[2]), "r"((a)[3]), "r"((b)[0]), "r"((b)[1]))

// ---------------- prep: x -> g_xa (single-level fp16) ----------------
__global__ void prep_x(const float* __restrict__ x) {
    int idx = blockIdx.x * blockDim.x + threadIdx.x;       // one u32 each
    if (idx >= 65536) return;
    int mt = idx >> 13;             // 8192 u32 per m-tile
    int c  = (idx >> 10) & 7;       // chunk 0..7
    int m  = (idx >> 3) & 127;
    int p  = idx & 7;
    int row = mt * 128 + m;
    int kb = c * 16 + 2 * p;
    g_xa[idx] = pack_h2(__float2half_rn(x[row * 128 + kb]),
                        __float2half_rn(x[row * 128 + kb + 1]));
}

// ---------------- main fused kernel ----------------
// grid (8 m-tiles, 128 nodes), 256 threads = 8 warps, 1 CTA/SM (~205 regs).
// Warp tile 32x64: warp_m = (wid&3)*32, warp_n = (wid>>2)*64.
// A fragments register-resident (whole kernel); B fragments double-buffered.
// B smem triple-buffered; tile t computes from buf t%3, stages t+2 into (t+2)%3.
// smem: B0 32KB | B1 32KB | B2 32KB | XA 32KB | Wg 512B | Wf 512B
#define SM_B0 0
#define SM_XA 98304
#define SM_WG 131072
#define SM_WF 131584
#define SM_TOT 132096

__global__ __launch_bounds__(256, 1)
void sde_main(const float* __restrict__ fw, const float* __restrict__ gw,
              const float* __restrict__ Wf, const float* __restrict__ bfv,
              const float* __restrict__ Wg, const float* __restrict__ bgv,
              float* __restrict__ fout, float* __restrict__ gout) {
    extern __shared__ char smem[];
    const uint32_t sb = smem_u32(smem);
    const int tid = threadIdx.x, l = tid & 31, wid = tid >> 5;
    const int i = blockIdx.y, b0 = blockIdx.x * 128;
    const int warp_m = (wid & 3) * 32;
    const int warp_n = (wid >> 2) * 64;
    float* Wg_s = (float*)(smem + SM_WG);
    float* Wf_s = (float*)(smem + SM_WF);

    // staging constants: pass p covers k-rows p*8 + wid; lane covers 4 fp32 cols
    const int ncol = l * 4;
    const uint32_t swb = (uint32_t)((l * 8) ^ (wid << 4));   // k mod 8 == wid

    // XA via cp.async (32KB)
    const char* asrc = (const char*)g_xa + (size_t)blockIdx.x * 32768;
#pragma unroll
    for (int j = 0; j < 8; ++j) {
        uint32_t off = (uint32_t)(j * 256 + tid) * 16;
        CP16(sb + SM_XA + off, asrc + off);
    }
    CP_COMMIT();

    // pre-stage B tiles 0 and 1 into bufs 0, 1
#pragma unroll
    for (int tt = 0; tt < 2; ++tt) {
        const float* w0 = gw + (size_t)i * 131072 + tt * 128;   // tiles 0,1 are g tiles
        uint32_t dst = (uint32_t)(tt * 32768);
#pragma unroll
        for (int pb = 0; pb < 4; ++pb) {
            float4 v[4];
#pragma unroll
            for (int q = 0; q < 4; ++q) {
                int k = (pb * 4 + q) * 8 + wid;
                v[q] = *reinterpret_cast<const float4*>(w0 + (size_t)k * 1024 + ncol);
            }
#pragma unroll
            for (int q = 0; q < 4; ++q) {
                int k = (pb * 4 + q) * 8 + wid;
                uint2 h;
                h.x = pack_h2(__float2half_rn(v[q].x), __float2half_rn(v[q].y));
                h.y = pack_h2(__float2half_rn(v[q].z), __float2half_rn(v[q].w));
                *reinterpret_cast<uint2*>(smem + dst + k * 256 + swb) = h;
            }
        }
    }
    if (tid < 128) { Wg_s[tid] = Wg[i * H_ + tid]; Wf_s[tid] = Wf[i * H_ + tid]; }
    CP_WAIT(0);
    __syncthreads();

    // fragment addressing constants
    const uint32_t aoff = (uint32_t)((warp_m + (l & 15)) * 32 + (l >> 4) * 16);
    const int kl   = (l & 7) + ((l >> 4) << 3);     // k-row within 16 for this lane
    const int jofs = (l >> 3) & 1;                  // n-block parity within LDM4T
    const int swl  = (l & 7) << 4;                  // swizzle term for LDM addresses

    // B-fragment loader (4 LDM4T) from buffer at smem offset bufoff, k-step s
#define LOADB(dst, bufoff, s_) do { \
        uint32_t kk_ = (uint32_t)((s_) * 16 + kl); \
        _Pragma("unroll") \
        for (int p_ = 0; p_ < 4; ++p_) { \
            uint32_t roff_ = (uint32_t)(((warp_n + p_ * 16 + jofs * 8) * 2) ^ swl); \
            LDM4T((dst)[2 * p_][0], (dst)[2 * p_ + 1][0], \
                  (dst)[2 * p_][1], (dst)[2 * p_ + 1][1], \
                  sb + (uint32_t)(bufoff) + kk_ * 256 + roff_); \
        } \
    } while (0)

    // A fragments: register-resident for all 8 k-steps (identical across tiles)
    uint32_t afr[8][2][4];
#pragma unroll
    for (int s = 0; s < 8; ++s)
#pragma unroll
        for (int im = 0; im < 2; ++im)
            LDM4(afr[s][im][0], afr[s][im][1], afr[s][im][2], afr[s][im][3],
                 sb + SM_XA + (uint32_t)(s * 4096) + aoff + im * 512);

    // B fragment double buffer; preload (tile 0, step 0)
    uint32_t bfb[2][8][2];
    LOADB(bfb[0], 0, 0);

    float accg[4][2], accf[4];
#pragma unroll
    for (int r = 0; r < 4; ++r) { accg[r][0] = 0.f; accg[r][1] = 0.f; accf[r] = 0.f; }

    uint32_t bufc = 0, bufn = 32768, bufs = 65536;   // rotate each tile

    for (int t = 0; t < NT; ++t) {
        const bool stg = (t <= NT - 3);              // stage tile t+2
        const float* wsrc = nullptr;
        int wstr = 0;
        if (stg) {
            if (t + 2 < 8) { wsrc = gw + (size_t)i * 131072 + (t + 2) * 128; wstr = 1024; }
            else           { wsrc = fw + (size_t)i * 16384;                  wstr = 128; }
        }

        float acc[8][2][4];
#pragma unroll
        for (int in = 0; in < 8; ++in)
#pragma unroll
            for (int im = 0; im < 2; ++im)
#pragma unroll
                for (int r = 0; r < 4; ++r) acc[in][im][r] = 0.f;

        float4 pa[2], pb2[2];

#pragma unroll
        for (int s = 0; s < 8; ++s) {
            // prefetch next step's B fragments (or next tile's step 0)
            if (s < 7) {
                LOADB(bfb[(s + 1) & 1], bufc, s + 1);
            } else if (t + 1 < NT) {
                LOADB(bfb[0], bufn, 0);
            }

            // staged W conversion for tile t+2 (2 passes/step, 2-step lookahead)
            if (stg) {
                if (s >= 2) {
                    int k0s = 2 * (s - 2) * 8 + wid;
                    uint2 h;
                    h.x = pack_h2(__float2half_rn(pa[s & 1].x), __float2half_rn(pa[s & 1].y));
                    h.y = pack_h2(__float2half_rn(pa[s & 1].z), __float2half_rn(pa[s & 1].w));
                    *reinterpret_cast<uint2*>(smem + bufs + k0s * 256 + swb) = h;
                    int k1s = k0s + 8;
                    h.x = pack_h2(__float2half_rn(pb2[s & 1].x), __float2half_rn(pb2[s & 1].y));
                    h.y = pack_h2(__float2half_rn(pb2[s & 1].z), __float2half_rn(pb2[s & 1].w));
                    *reinterpret_cast<uint2*>(smem + bufs + k1s * 256 + swb) = h;
                }
                int k0 = (2 * s) * 8 + wid;
                pa[s & 1]  = *reinterpret_cast<const float4*>(wsrc + (size_t)k0 * wstr + ncol);
                pb2[s & 1] = *reinterpret_cast<const float4*>(wsrc + (size_t)(k0 + 8) * wstr + ncol);
            }

            // MMAs for step s (fragments already resident)
#pragma unroll
            for (int im = 0; im < 2; ++im)
#pragma unroll
                for (int in = 0; in < 8; ++in)
                    MMA16816(acc[in][im], afr[s][im], bfb[s & 1][in]);
        }

        // flush staged passes 12..15 (loaded at steps 6,7)
        if (stg) {
#pragma unroll
            for (int q = 0; q < 2; ++q) {
                int k0s = (12 + 2 * q) * 8 + wid;
                uint2 h;
                h.x = pack_h2(__float2half_rn(pa[q].x), __float2half_rn(pa[q].y));
                h.y = pack_h2(__float2half_rn(pa[q].z), __float2half_rn(pa[q].w));
                *reinterpret_cast<uint2*>(smem + bufs + k0s * 256 + swb) = h;
                int k1s = k0s + 8;
                h.x = pack_h2(__float2half_rn(pb2[q].x), __float2half_rn(pb2[q].y));
                h.y = pack_h2(__float2half_rn(pb2[q].z), __float2half_rn(pb2[q].w));
                *reinterpret_cast<uint2*>(smem + bufs + k1s * 256 + swb) = h;
            }
        }

        // fused epilogue
        if (t < 8) {
            const int hb = t * 16 + (wid >> 2) * 8;
#pragma unroll
            for (int in = 0; in < 8; ++in) {
                const float w = Wg_s[hb + in];
#pragma unroll
                for (int im = 0; im < 2; ++im) {
                    accg[im * 2][0]     = fmaf(w, elu1(acc[in][im][0]), accg[im * 2][0]);
                    accg[im * 2][1]     = fmaf(w, elu1(acc[in][im][1]), accg[im * 2][1]);
                    accg[im * 2 + 1][0] = fmaf(w, elu1(acc[in][im][2]), accg[im * 2 + 1][0]);
                    accg[im * 2 + 1][1] = fmaf(w, elu1(acc[in][im][3]), accg[im * 2 + 1][1]);
                }
            }
        } else {
            const int cb = warp_n + 2 * (l & 3);
#pragma unroll
            for (int in = 0; in < 8; ++in) {
                const float w0 = Wf_s[cb + in * 8], w1 = Wf_s[cb + in * 8 + 1];
#pragma unroll
                for (int im = 0; im < 2; ++im) {
                    accf[im * 2]     += w0 * elu1(acc[in][im][0]) + w1 * elu1(acc[in][im][1]);
                    accf[im * 2 + 1] += w0 * elu1(acc[in][im][2]) + w1 * elu1(acc[in][im][3]);
                }
            }
        }
        __syncthreads();   // staged buffer complete; buffer rotation safe

        uint32_t old = bufc; bufc = bufn; bufn = bufs; bufs = old;
    }

    // cross-warp reduction: n-warps 4-7 hand partials to warps 0-3
    float* red = (float*)smem;                 // reuse B region
    const int base = ((wid & 3) * 32 + l) * 12;
    if (wid >= 4) {
#pragma unroll
        for (int r = 0; r < 4; ++r) {
            red[base + r * 2]     = accg[r][0];
            red[base + r * 2 + 1] = accg[r][1];
            red[base + 8 + r]     = accf[r];
        }
    }
    __syncthreads();
    if (wid < 4) {
        const float bgi = bgv[i], bfi = bfv[i];
#pragma unroll
        for (int r = 0; r < 4; ++r) {
            float g0 = accg[r][0] + red[base + r * 2];
            float g1 = accg[r][1] + red[base + r * 2 + 1];
            float vf = accf[r] + red[base + 8 + r];
            const int row = b0 + warp_m + (r >> 1) * 16 + (r & 1) * 8 + (l >> 2);
            *reinterpret_cast<float2*>(gout + ((size_t)row * 128 + i) * 8 + 2 * (l & 3)) =
                make_float2(g0 + bgi, g1 + bgi);
            vf += __shfl_xor_sync(0xffffffffu, vf, 1);
            vf += __shfl_xor_sync(0xffffffffu, vf, 2);
            if ((l & 3) == 0) fout[(size_t)row * 128 + i] = vf + bfi;
        }
    }
}

// ---------------- launch ----------------
extern "C" void kernel_launch(void* const* d_in, const int* in_sizes, int n_in,
                              void* d_out, int out_size) {
    (void)in_sizes; (void)n_in; (void)out_size;
    const float* x  = (const float*)d_in[0];
    const float* fw = (const float*)d_in[1];
    const float* gw = (const float*)d_in[2];
    const float* Wf = (const float*)d_in[3];
    const float* bf = (const float*)d_in[4];
    const float* Wg = (const float*)d_in[5];
    const float* bg = (const float*)d_in[6];
    float* out  = (float*)d_out;
    float* fout = out;                      // [B,N]
    float* gout = out + (size_t)B_ * N_;    // [B,N,D]

    static bool attr_set = false;
    if (!attr_set) {
        cudaFuncSetAttribute(sde_main, cudaFuncAttributeMaxDynamicSharedMemorySize, SM_TOT);
        attr_set = true;
    }

    prep_x<<<256, 256>>>(x);
    sde_main<<<dim3(8, N_), 256, SM_TOT>>>(fw, gw, Wf, bf, Wg, bg, fout, gout);
}

// round 15
// speedup vs baseline: 1.3498x; 1.3498x over previous
#include <cuda_runtime.h>
#include <cuda_fp16.h>
#include <cstdint>

#define B_ 1024
#define N_ 128
#define H_ 128
#define D_ 8
#define NT 9   // 8 g col-tiles (128 cols) + 1 f tile
#define LOG2E 1.4426950408889634f
#define LN2   0.6931471805599453f

// Packed X operand (prep_x writes, main reads) — values pre-scaled by log2e
// g_xa: [mtile 8][chunk 8][m 128][k16] fp16 pairs
__device__ __align__(16) unsigned g_xa[8 * 8 * 128 * 8];           // 256KB

// ---------------- helpers ----------------
__device__ __forceinline__ uint32_t smem_u32(const void* p) {
    uint32_t a;
    asm("{ .reg .u64 t; cvta.to.shared.u64 t, %1; cvt.u32.u64 %0, t; }" : "=r"(a) : "l"(p));
    return a;
}
__device__ __forceinline__ unsigned pack_h2(float f0, float f1) {
    __half2 t = __floats2half2_rn(f0, f1);
    return *reinterpret_cast<unsigned*>(&t);
}
__device__ __forceinline__ float elu1(float x) {
    return x > 0.0f ? x : (__expf(x) - 1.0f);
}
__device__ __forceinline__ float ex2(float x) {
    float r;
    asm("ex2.approx.ftz.f32 %0, %1;" : "=f"(r) : "f"(x));
    return r;
}

#define CP16(s, g) asm volatile("cp.async.cg.shared.global [%0], [%1], 16;" :: "r"(s), "l"(g))
#define CP_COMMIT() asm volatile("cp.async.commit_group;" ::: "memory")
#define CP_WAIT(n)  asm volatile("cp.async.wait_group %0;" :: "n"(n) : "memory")

#define LDM4(r0, r1, r2, r3, a) \
    asm volatile("ldmatrix.sync.aligned.m8n8.x4.shared.b16 {%0,%1,%2,%3}, [%4];" \
        : "=r"(r0), "=r"(r1), "=r"(r2), "=r"(r3) : "r"(a))

#define LDM4T(r0, r1, r2, r3, a) \
    asm volatile("ldmatrix.sync.aligned.m8n8.x4.trans.shared.b16 {%0,%1,%2,%3}, [%4];" \
        : "=r"(r0), "=r"(r1), "=r"(r2), "=r"(r3) : "r"(a))

#define MMA16816(c, a, b) \
    asm volatile("mma.sync.aligned.m16n8k16.row.col.f32.f16.f16.f32 " \
        "{%0,%1,%2,%3}, {%4,%5,%6,%7}, {%8,%9}, {%0,%1,%2,%3};" \
        : "+f"((c)[0]), "+f"((c)[1]), "+f"((c)[2]), "+f"((c)[3]) \
        : "r"((a)[0]), "r"((a)[1]), "r"((a)[2]), "r"((a)[3]), "r"((b)[0]), "r"((b)[1]))

// zero a 4-float accumulator quad via one LDS.128 from the zero block
#define ZACC(q, zaddr) \
    asm volatile("ld.shared.v4.f32 {%0,%1,%2,%3}, [%4];" \
        : "=f"((q)[0]), "=f"((q)[1]), "=f"((q)[2]), "=f"((q)[3]) : "r"(zaddr))

// ---------------- prep: x -> g_xa (fp16, pre-scaled by log2e) ----------------
__global__ void prep_x(const float* __restrict__ x) {
    int idx = blockIdx.x * blockDim.x + threadIdx.x;       // one u32 each
    if (idx >= 65536) return;
    int mt = idx >> 13;             // 8192 u32 per m-tile
    int c  = (idx >> 10) & 7;       // chunk 0..7
    int m  = (idx >> 3) & 127;
    int p  = idx & 7;
    int row = mt * 128 + m;
    int kb = c * 16 + 2 * p;
    g_xa[idx] = pack_h2(x[row * 128 + kb] * LOG2E, x[row * 128 + kb + 1] * LOG2E);
}

// ---------------- main fused kernel (R12 base) ----------------
// grid (8 m-tiles, 128 nodes), 256 threads = 8 warps, 2 CTAs/SM.
// Warp tile 32x64: warp_m = (wid&3)*32, warp_n = (wid>>2)*64.
// smem: B0 32KB | B1 32KB | XA 32KB | Wg 512B | Wf 512B | Z 32B
#define SM_B0 0
#define SM_B1 32768
#define SM_XA 65536
#define SM_WG 98304
#define SM_WF 98816
#define SM_Z  99328
#define SM_TOT 99360

__global__ __launch_bounds__(256, 2)
void sde_main(const float* __restrict__ fw, const float* __restrict__ gw,
              const float* __restrict__ Wf, const float* __restrict__ bfv,
              const float* __restrict__ Wg, const float* __restrict__ bgv,
              float* __restrict__ fout, float* __restrict__ gout) {
    extern __shared__ char smem[];
    const uint32_t sb = smem_u32(smem);
    const int tid = threadIdx.x, l = tid & 31, wid = tid >> 5;
    const int i = blockIdx.y, b0 = blockIdx.x * 128;
    const int warp_m = (wid & 3) * 32;
    const int warp_n = (wid >> 2) * 64;
    float* Wg_s = (float*)(smem + SM_WG);
    float* Wf_s = (float*)(smem + SM_WF);
    const uint32_t zaddr = sb + SM_Z;

    // staging constants: pass p covers k-rows p*8 + wid; lane covers 4 fp32 cols
    const int ncol = l * 4;
    const uint32_t swb = (uint32_t)((l * 8) ^ (wid << 4));

    // XA via cp.async (32KB)
    const char* asrc = (const char*)g_xa + (size_t)blockIdx.x * 32768;
#pragma unroll
    for (int j = 0; j < 8; ++j) {
        uint32_t off = (uint32_t)(j * 256 + tid) * 16;
        CP16(sb + SM_XA + off, asrc + off);
    }
    CP_COMMIT();

    // pre-stage B tile 0 (g tile 0: cols 0..127, row stride 1024)
    {
        const float* w0 = gw + (size_t)i * 131072;
#pragma unroll
        for (int pb = 0; pb < 4; ++pb) {
            float4 v[4];
#pragma unroll
            for (int q = 0; q < 4; ++q) {
                int k = (pb * 4 + q) * 8 + wid;
                v[q] = *reinterpret_cast<const float4*>(w0 + (size_t)k * 1024 + ncol);
            }
#pragma unroll
            for (int q = 0; q < 4; ++q) {
                int k = (pb * 4 + q) * 8 + wid;
                uint2 h;
                h.x = pack_h2(v[q].x, v[q].y);
                h.y = pack_h2(v[q].z, v[q].w);
                *reinterpret_cast<uint2*>(smem + SM_B0 + k * 256 + swb) = h;
            }
        }
    }
    if (tid < 128) { Wg_s[tid] = Wg[i * H_ + tid]; Wf_s[tid] = Wf[i * H_ + tid]; }
    if (tid < 4) ((float*)(smem + SM_Z))[tid] = 0.0f;
    CP_WAIT(0);
    __syncthreads();

    // sumWg = sum_h Wg[i,h]  (for the folded "-1" elu term)
    if (wid == 0) {
        float sv = Wg_s[l] + Wg_s[l + 32] + Wg_s[l + 64] + Wg_s[l + 96];
#pragma unroll
        for (int o = 16; o; o >>= 1) sv += __shfl_xor_sync(0xffffffffu, sv, o);
        if (l == 0) *(float*)(smem + SM_Z + 16) = sv;
    }

    // fragment addressing constants
    const uint32_t aoff = (uint32_t)((warp_m + (l & 15)) * 32 + (l >> 4) * 16);
    const int kl   = (l & 7) + ((l >> 4) << 3);
    const int jofs = (l >> 3) & 1;
    const int swl  = (l & 7) << 4;

    float gA[4][2], gB[4][2], accf[4];
#pragma unroll
    for (int r = 0; r < 4; ++r) {
        gA[r][0] = 0.f; gA[r][1] = 0.f;
        gB[r][0] = 0.f; gB[r][1] = 0.f;
        accf[r] = 0.f;
    }

    for (int t = 0; t < NT; ++t) {
        const uint32_t bbase = (uint32_t)((t & 1) ? SM_B1 : SM_B0);
        const uint32_t sbase = (uint32_t)((t & 1) ? SM_B0 : SM_B1);   // staging target (t+1)
        const bool stg = (t + 1 < NT);
        const float* wsrc = nullptr;
        int wstr = 0;
        if (stg) {
            if (t + 1 < 8) { wsrc = gw + (size_t)i * 131072 + (t + 1) * 128; wstr = 1024; }
            else           { wsrc = fw + (size_t)i * 16384;                  wstr = 128; }
        }

        float acc[8][2][4];
#pragma unroll
        for (int in = 0; in < 8; ++in)
#pragma unroll
            for (int im = 0; im < 2; ++im)
                ZACC(acc[in][im], zaddr);

        float4 pa, pb2;

#pragma unroll
        for (int s = 0; s < 8; ++s) {
            // staged W conversion for tile t+1 (single-depth, lookahead 1 step)
            if (stg) {
                if (s >= 1) {
                    int k0s = 2 * (s - 1) * 8 + wid;
                    uint2 h;
                    h.x = pack_h2(pa.x, pa.y);
                    h.y = pack_h2(pa.z, pa.w);
                    *reinterpret_cast<uint2*>(smem + sbase + k0s * 256 + swb) = h;
                    int k1s = k0s + 8;
                    h.x = pack_h2(pb2.x, pb2.y);
                    h.y = pack_h2(pb2.z, pb2.w);
                    *reinterpret_cast<uint2*>(smem + sbase + k1s * 256 + swb) = h;
                }
                int k0 = (2 * s) * 8 + wid;
                pa  = *reinterpret_cast<const float4*>(wsrc + (size_t)k0 * wstr + ncol);
                pb2 = *reinterpret_cast<const float4*>(wsrc + (size_t)(k0 + 8) * wstr + ncol);
            }

            // MMA step
            const uint32_t ab = sb + SM_XA + (uint32_t)(s * 4096) + aoff;
            uint32_t af[2][4], bfr[8][2];
#pragma unroll
            for (int im = 0; im < 2; ++im)
                LDM4(af[im][0], af[im][1], af[im][2], af[im][3], ab + im * 512);
#pragma unroll
            for (int p = 0; p < 4; ++p) {
                uint32_t kk = (uint32_t)(s * 16 + kl);
                uint32_t roff = (uint32_t)(((warp_n + p * 16 + jofs * 8) * 2) ^ swl);
                LDM4T(bfr[2 * p][0], bfr[2 * p + 1][0],
                      bfr[2 * p][1], bfr[2 * p + 1][1],
                      sb + bbase + kk * 256 + roff);
            }
#pragma unroll
            for (int im = 0; im < 2; ++im)
#pragma unroll
                for (int in = 0; in < 8; ++in)
                    MMA16816(acc[in][im], af[im], bfr[in]);
        }

        // flush staged passes 14,15 (loaded at step 7)
        if (stg) {
            int k0s = 14 * 8 + wid;
            uint2 h;
            h.x = pack_h2(pa.x, pa.y);
            h.y = pack_h2(pa.z, pa.w);
            *reinterpret_cast<uint2*>(smem + sbase + k0s * 256 + swb) = h;
            int k1s = k0s + 8;
            h.x = pack_h2(pb2.x, pb2.y);
            h.y = pack_h2(pb2.z, pb2.w);
            *reinterpret_cast<uint2*>(smem + sbase + k1s * 256 + swb) = h;
        }

        // fused epilogue — acc holds x' = log2e * temp
        if (t < 8) {
            const int hb = t * 16 + (wid >> 2) * 8;
#pragma unroll
            for (int in = 0; in < 8; ++in) {
                const float w = Wg_s[hb + in];
#pragma unroll
                for (int im = 0; im < 2; ++im) {
#pragma unroll
                    for (int r = 0; r < 4; ++r) {
                        float v = acc[in][im][r];
                        float mx = fmaxf(v, 0.0f);
                        float e  = ex2(fminf(v, 0.0f));
                        const int slot = im * 2 + (r >> 1), pcol = r & 1;
                        gA[slot][pcol] = fmaf(w, mx, gA[slot][pcol]);
                        gB[slot][pcol] = fmaf(w, e,  gB[slot][pcol]);
                    }
                }
            }
        } else {
            const int cb = warp_n + 2 * (l & 3);
#pragma unroll
            for (int in = 0; in < 8; ++in) {
                const float w0 = Wf_s[cb + in * 8], w1 = Wf_s[cb + in * 8 + 1];
#pragma unroll
                for (int im = 0; im < 2; ++im) {
                    accf[im * 2]     += w0 * elu1(acc[in][im][0] * LN2) +
                                        w1 * elu1(acc[in][im][1] * LN2);
                    accf[im * 2 + 1] += w0 * elu1(acc[in][im][2] * LN2) +
                                        w1 * elu1(acc[in][im][3] * LN2);
                }
            }
        }
        __syncthreads();   // staged buffer complete + everyone done reading bbase
    }

    // cross-warp reduction: n-warps 4-7 hand combined partials to warps 0-3
    float* red = (float*)smem;                 // reuse B region (Z block untouched)
    const int base = ((wid & 3) * 32 + l) * 12;
    if (wid >= 4) {
#pragma unroll
        for (int r = 0; r < 4; ++r) {
            red[base + r * 2]     = fmaf(gA[r][0], LN2, gB[r][0]);
            red[base + r * 2 + 1] = fmaf(gA[r][1], LN2, gB[r][1]);
            red[base + 8 + r]     = accf[r];
        }
    }
    __syncthreads();
    if (wid < 4) {
        const float bgi = bgv[i], bfi = bfv[i];
        const float sumWg = *(const float*)(smem + SM_Z + 16);
#pragma unroll
        for (int r = 0; r < 4; ++r) {
            float g0 = fmaf(gA[r][0], LN2, gB[r][0]) + red[base + r * 2]     - sumWg;
            float g1 = fmaf(gA[r][1], LN2, gB[r][1]) + red[base + r * 2 + 1] - sumWg;
            float vf = accf[r] + red[base + 8 + r];
            const int row = b0 + warp_m + (r >> 1) * 16 + (r & 1) * 8 + (l >> 2);
            *reinterpret_cast<float2*>(gout + ((size_t)row * 128 + i) * 8 + 2 * (l & 3)) =
                make_float2(g0 + bgi, g1 + bgi);
            vf += __shfl_xor_sync(0xffffffffu, vf, 1);
            vf += __shfl_xor_sync(0xffffffffu, vf, 2);
            if ((l & 3) == 0) fout[(size_t)row * 128 + i] = vf + bfi;
        }
    }
}

// ---------------- launch ----------------
extern "C" void kernel_launch(void* const* d_in, const int* in_sizes, int n_in,
                              void* d_out, int out_size) {
    (void)in_sizes; (void)n_in; (void)out_size;
    const float* x  = (const float*)d_in[0];
    const float* fw = (const float*)d_in[1];
    const float* gw = (const float*)d_in[2];
    const float* Wf = (const float*)d_in[3];
    const float* bf = (const float*)d_in[4];
    const float* Wg = (const float*)d_in[5];
    const float* bg = (const float*)d_in[6];
    float* out  = (float*)d_out;
    float* fout = out;                      // [B,N]
    float* gout = out + (size_t)B_ * N_;    // [B,N,D]

    static bool attr_set = false;
    if (!attr_set) {
        cudaFuncSetAttribute(sde_main, cudaFuncAttributeMaxDynamicSharedMemorySize, SM_TOT);
        attr_set = true;
    }

    prep_x<<<256, 256>>>(x);
    sde_main<<<dim3(8, N_), 256, SM_TOT>>>(fw, gw, Wf, bf, Wg, bg, fout, gout);
}

// round 16
// speedup vs baseline: 1.4482x; 1.0729x over previous
#include <cuda_runtime.h>
#include <cuda_fp16.h>
#include <cstdint>

#define B_ 1024
#define N_ 128
#define H_ 128
#define D_ 8
#define NT 9   // 8 g col-tiles (128 cols) + 1 f tile
#define LOG2E 1.4426950408889634f
#define LN2   0.6931471805599453f

// Packed X operand (prep_x writes, main reads) — values pre-scaled by log2e
// g_xa: [mtile 8][chunk 8][m 128][k16] fp16 pairs
__device__ __align__(16) unsigned g_xa[8 * 8 * 128 * 8];           // 256KB

// ---------------- helpers ----------------
__device__ __forceinline__ uint32_t smem_u32(const void* p) {
    uint32_t a;
    asm("{ .reg .u64 t; cvta.to.shared.u64 t, %1; cvt.u32.u64 %0, t; }" : "=r"(a) : "l"(p));
    return a;
}
__device__ __forceinline__ unsigned pack_h2(float f0, float f1) {
    __half2 t = __floats2half2_rn(f0, f1);
    return *reinterpret_cast<unsigned*>(&t);
}
__device__ __forceinline__ float elu1(float x) {
    return x > 0.0f ? x : (__expf(x) - 1.0f);
}
__device__ __forceinline__ float ex2(float x) {
    float r;
    asm("ex2.approx.ftz.f32 %0, %1;" : "=f"(r) : "f"(x));
    return r;
}

#define CP16(s, g) asm volatile("cp.async.cg.shared.global [%0], [%1], 16;" :: "r"(s), "l"(g))
#define CP_COMMIT() asm volatile("cp.async.commit_group;" ::: "memory")
#define CP_WAIT(n)  asm volatile("cp.async.wait_group %0;" :: "n"(n) : "memory")

#define LDM4(r0, r1, r2, r3, a) \
    asm volatile("ldmatrix.sync.aligned.m8n8.x4.shared.b16 {%0,%1,%2,%3}, [%4];" \
        : "=r"(r0), "=r"(r1), "=r"(r2), "=r"(r3) : "r"(a))

#define LDM4T(r0, r1, r2, r3, a) \
    asm volatile("ldmatrix.sync.aligned.m8n8.x4.trans.shared.b16 {%0,%1,%2,%3}, [%4];" \
        : "=r"(r0), "=r"(r1), "=r"(r2), "=r"(r3) : "r"(a))

#define MMA16816(c, a, b) \
    asm volatile("mma.sync.aligned.m16n8k16.row.col.f32.f16.f16.f32 " \
        "{%0,%1,%2,%3}, {%4,%5,%6,%7}, {%8,%9}, {%0,%1,%2,%3};" \
        : "+f"((c)[0]), "+f"((c)[1]), "+f"((c)[2]), "+f"((c)[3]) \
        : "r"((a)[0]), "r"((a)[1]), "r"((a)[2]), "r"((a)[3]), "r"((b)[0]), "r"((b)[1]))

#define ZACC(q, zaddr) \
    asm volatile("ld.shared.v4.f32 {%0,%1,%2,%3}, [%4];" \
        : "=f"((q)[0]), "=f"((q)[1]), "=f"((q)[2]), "=f"((q)[3]) : "r"(zaddr))

// ---------------- prep: x -> g_xa (fp16, pre-scaled by log2e) ----------------
__global__ void prep_x(const float* __restrict__ x) {
    int idx = blockIdx.x * blockDim.x + threadIdx.x;       // one u32 each
    if (idx >= 65536) return;
    int mt = idx >> 13;             // 8192 u32 per m-tile
    int c  = (idx >> 10) & 7;       // chunk 0..7
    int m  = (idx >> 3) & 127;
    int p  = idx & 7;
    int row = mt * 128 + m;
    int kb = c * 16 + 2 * p;
    g_xa[idx] = pack_h2(x[row * 128 + kb] * LOG2E, x[row * 128 + kb + 1] * LOG2E);
}

// ---------------- main fused kernel ----------------
// grid (8 m-tiles, 128 nodes), 256 threads = 8 warps, 2 CTAs/SM.
// Warp tile 32x64 processed as two 32x32 n-halves; A/B fragments double-
// buffered (software pipeline); W staging fused with 2-step lookahead.
// smem: B0 32KB | B1 32KB | XA 32KB | Wg 512B | Wf 512B | Z 32B
#define SM_B0 0
#define SM_B1 32768
#define SM_XA 65536
#define SM_WG 98304
#define SM_WF 98816
#define SM_Z  99328
#define SM_TOT 99360

__global__ __launch_bounds__(256, 2)
void sde_main(const float* __restrict__ fw, const float* __restrict__ gw,
              const float* __restrict__ Wf, const float* __restrict__ bfv,
              const float* __restrict__ Wg, const float* __restrict__ bgv,
              float* __restrict__ fout, float* __restrict__ gout) {
    extern __shared__ char smem[];
    const uint32_t sb = smem_u32(smem);
    const int tid = threadIdx.x, l = tid & 31, wid = tid >> 5;
    const int i = blockIdx.y, b0 = blockIdx.x * 128;
    const int warp_m = (wid & 3) * 32;
    const int warp_n = (wid >> 2) * 64;
    float* Wg_s = (float*)(smem + SM_WG);
    float* Wf_s = (float*)(smem + SM_WF);
    const uint32_t zaddr = sb + SM_Z;

    // staging constants: global pass u covers k-row u*8 + wid; lane = 4 fp32 cols
    const int ncol = l * 4;
    const uint32_t swb = (uint32_t)((l * 8) ^ (wid << 4));

    // XA via cp.async (32KB)
    const char* asrc = (const char*)g_xa + (size_t)blockIdx.x * 32768;
#pragma unroll
    for (int j = 0; j < 8; ++j) {
        uint32_t off = (uint32_t)(j * 256 + tid) * 16;
        CP16(sb + SM_XA + off, asrc + off);
    }
    CP_COMMIT();

    // pre-stage B tile 0 (g tile 0: cols 0..127, row stride 1024)
    {
        const float* w0 = gw + (size_t)i * 131072;
#pragma unroll
        for (int pb = 0; pb < 4; ++pb) {
            float4 v[4];
#pragma unroll
            for (int q = 0; q < 4; ++q) {
                int k = (pb * 4 + q) * 8 + wid;
                v[q] = *reinterpret_cast<const float4*>(w0 + (size_t)k * 1024 + ncol);
            }
#pragma unroll
            for (int q = 0; q < 4; ++q) {
                int k = (pb * 4 + q) * 8 + wid;
                uint2 h;
                h.x = pack_h2(v[q].x, v[q].y);
                h.y = pack_h2(v[q].z, v[q].w);
                *reinterpret_cast<uint2*>(smem + SM_B0 + k * 256 + swb) = h;
            }
        }
    }
    if (tid < 128) { Wg_s[tid] = Wg[i * H_ + tid]; Wf_s[tid] = Wf[i * H_ + tid]; }
    if (tid < 4) ((float*)(smem + SM_Z))[tid] = 0.0f;
    CP_WAIT(0);
    __syncthreads();

    // sumWg = sum_h Wg[i,h]  (folded "-1" elu term)
    if (wid == 0) {
        float sv = Wg_s[l] + Wg_s[l + 32] + Wg_s[l + 64] + Wg_s[l + 96];
#pragma unroll
        for (int o = 16; o; o >>= 1) sv += __shfl_xor_sync(0xffffffffu, sv, o);
        if (l == 0) *(float*)(smem + SM_Z + 16) = sv;
    }

    // fragment addressing constants
    const uint32_t aoff = (uint32_t)((warp_m + (l & 15)) * 32 + (l >> 4) * 16);
    const int kl   = (l & 7) + ((l >> 4) << 3);
    const int jofs = (l >> 3) & 1;
    const int swl  = (l & 7) << 4;

    // A loader (2 LDM4) for k-step s_
#define LDA2(dst, s_) do { \
        _Pragma("unroll") \
        for (int im_ = 0; im_ < 2; ++im_) \
            LDM4((dst)[im_][0], (dst)[im_][1], (dst)[im_][2], (dst)[im_][3], \
                 sb + SM_XA + (uint32_t)((s_) * 4096) + aoff + im_ * 512); \
    } while (0)
    // B loader (2 LDM4T) from buffer bufoff_, n-base nb_, k-step s_
#define LDB2(dst, bufoff_, nb_, s_) do { \
        uint32_t kk_ = (uint32_t)((s_) * 16 + kl); \
        _Pragma("unroll") \
        for (int p_ = 0; p_ < 2; ++p_) { \
            uint32_t roff_ = (uint32_t)((((nb_) + p_ * 16 + jofs * 8) * 2) ^ swl); \
            LDM4T((dst)[2 * p_][0], (dst)[2 * p_ + 1][0], \
                  (dst)[2 * p_][1], (dst)[2 * p_ + 1][1], \
                  sb + (uint32_t)(bufoff_) + kk_ * 256 + roff_); \
        } \
    } while (0)
    // staging STS of pass u_ from float4 src_
#define STSW(u_, src_) do { \
        int k_ = (u_) * 8 + wid; \
        uint2 h_; \
        h_.x = pack_h2((src_).x, (src_).y); \
        h_.y = pack_h2((src_).z, (src_).w); \
        *reinterpret_cast<uint2*>(smem + sbase + k_ * 256 + swb) = h_; \
    } while (0)

    float accg[4][2], accf[4];
#pragma unroll
    for (int r = 0; r < 4; ++r) {
        accg[r][0] = 0.f; accg[r][1] = 0.f; accf[r] = 0.f;
    }

    for (int t = 0; t < NT; ++t) {
        const uint32_t bbase = (uint32_t)((t & 1) ? SM_B1 : SM_B0);
        const uint32_t sbase = (uint32_t)((t & 1) ? SM_B0 : SM_B1);
        const bool stg = (t + 1 < NT);
        const float* wsrc = nullptr;
        int wstr = 0;
        if (stg) {
            if (t + 1 < 8) { wsrc = gw + (size_t)i * 131072 + (t + 1) * 128; wstr = 1024; }
            else           { wsrc = fw + (size_t)i * 16384;                  wstr = 128; }
        }

        uint32_t af[2][2][4], bfr[2][4][2];
        float4 pa[2];

        // preload half 0, step 0
        LDA2(af[0], 0);
        LDB2(bfr[0], bbase, warp_n, 0);

#pragma unroll
        for (int half = 0; half < 2; ++half) {
            const int nb = warp_n + half * 32;
            float acc[4][2][4];
#pragma unroll
            for (int in = 0; in < 4; ++in)
#pragma unroll
                for (int im = 0; im < 2; ++im)
                    ZACC(acc[in][im], zaddr);

#pragma unroll
            for (int s = 0; s < 8; ++s) {
                const int u = half * 8 + s;
                // prefetch next step's fragments (or half 1 step 0)
                if (s < 7) {
                    LDA2(af[(s + 1) & 1], s + 1);
                    LDB2(bfr[(s + 1) & 1], bbase, nb, s + 1);
                } else if (half == 0) {
                    LDA2(af[0], 0);
                    LDB2(bfr[0], bbase, warp_n + 32, 0);
                }
                // staged W conversion for tile t+1 (1 pass/step, 2-step lookahead)
                if (stg) {
                    if (u >= 2) STSW(u - 2, pa[u & 1]);
                    int k = u * 8 + wid;
                    pa[u & 1] = *reinterpret_cast<const float4*>(
                        wsrc + (size_t)k * wstr + ncol);
                }
                // MMAs for step s
#pragma unroll
                for (int im = 0; im < 2; ++im)
#pragma unroll
                    for (int in = 0; in < 4; ++in)
                        MMA16816(acc[in][im], af[s & 1][im], bfr[s & 1][in]);
            }

            if (stg && half == 1) {    // flush passes 14, 15
                STSW(14, pa[0]);
                STSW(15, pa[1]);
            }

            // fused epilogue for this 32-col half — acc holds x' = log2e*temp
            if (t < 8) {
                const int hb = t * 16 + (wid >> 2) * 8 + half * 4;
#pragma unroll
                for (int in = 0; in < 4; ++in) {
                    const float w = Wg_s[hb + in];
#pragma unroll
                    for (int im = 0; im < 2; ++im) {
#pragma unroll
                        for (int r = 0; r < 4; ++r) {
                            float v = acc[in][im][r];
                            float mx = fmaxf(v, 0.0f);
                            float e  = ex2(fminf(v, 0.0f));
                            const int slot = im * 2 + (r >> 1), pcol = r & 1;
                            accg[slot][pcol] =
                                fmaf(w, fmaf(mx, LN2, e), accg[slot][pcol]);
                        }
                    }
                }
            } else {
                const int cb = nb + 2 * (l & 3);
#pragma unroll
                for (int in = 0; in < 4; ++in) {
                    const float w0 = Wf_s[cb + in * 8], w1 = Wf_s[cb + in * 8 + 1];
#pragma unroll
                    for (int im = 0; im < 2; ++im) {
                        accf[im * 2]     += w0 * elu1(acc[in][im][0] * LN2) +
                                            w1 * elu1(acc[in][im][1] * LN2);
                        accf[im * 2 + 1] += w0 * elu1(acc[in][im][2] * LN2) +
                                            w1 * elu1(acc[in][im][3] * LN2);
                    }
                }
            }
        }
        __syncthreads();   // staged buffer complete + all reads of bbase done
    }

    // cross-warp reduction: n-warps 4-7 hand partials to warps 0-3
    float* red = (float*)smem;                 // reuse B region (Z block untouched)
    const int base = ((wid & 3) * 32 + l) * 12;
    if (wid >= 4) {
#pragma unroll
        for (int r = 0; r < 4; ++r) {
            red[base + r * 2]     = accg[r][0];
            red[base + r * 2 + 1] = accg[r][1];
            red[base + 8 + r]     = accf[r];
        }
    }
    __syncthreads();
    if (wid < 4) {
        const float bgi = bgv[i], bfi = bfv[i];
        const float sumWg = *(const float*)(smem + SM_Z + 16);
#pragma unroll
        for (int r = 0; r < 4; ++r) {
            float g0 = accg[r][0] + red[base + r * 2]     - sumWg;
            float g1 = accg[r][1] + red[base + r * 2 + 1] - sumWg;
            float vf = accf[r] + red[base + 8 + r];
            const int row = b0 + warp_m + (r >> 1) * 16 + (r & 1) * 8 + (l >> 2);
            *reinterpret_cast<float2*>(gout + ((size_t)row * 128 + i) * 8 + 2 * (l & 3)) =
                make_float2(g0 + bgi, g1 + bgi);
            vf += __shfl_xor_sync(0xffffffffu, vf, 1);
            vf += __shfl_xor_sync(0xffffffffu, vf, 2);
            if ((l & 3) == 0) fout[(size_t)row * 128 + i] = vf + bfi;
        }
    }
}

// ---------------- launch ----------------
extern "C" void kernel_launch(void* const* d_in, const int* in_sizes, int n_in,
                              void* d_out, int out_size) {
    (void)in_sizes; (void)n_in; (void)out_size;
    const float* x  = (const float*)d_in[0];
    const float* fw = (const float*)d_in[1];
    const float* gw = (const float*)d_in[2];
    const float* Wf = (const float*)d_in[3];
    const float* bf = (const float*)d_in[4];
    const float* Wg = (const float*)d_in[5];
    const float* bg = (const float*)d_in[6];
    float* out  = (float*)d_out;
    float* fout = out;                      // [B,N]
    float* gout = out + (size_t)B_ * N_;    // [B,N,D]

    static bool attr_set = false;
    if (!attr_set) {
        cudaFuncSetAttribute(sde_main, cudaFuncAttributeMaxDynamicSharedMemorySize, SM_TOT);
        attr_set = true;
    }

    prep_x<<<256, 256>>>(x);
    sde_main<<<dim3(8, N_), 256, SM_TOT>>>(fw, gw, Wf, bf, Wg, bg, fout, gout);
}

// round 17
// speedup vs baseline: 1.6732x; 1.1554x over previous
#include <cuda_runtime.h>
#include <cuda_fp16.h>
#include <cstdint>

#define B_ 1024
#define N_ 128
#define H_ 128
#define D_ 8
#define NT 9   // 8 g col-tiles (128 cols) + 1 f tile
#define LOG2E 1.4426950408889634f
#define LN2   0.6931471805599453f

// Packed X operand (prep_x writes) — values pre-scaled by log2e
// g_xa: [mtile 8][chunk 8][m 128][k16] fp16 pairs
__device__ __align__(16) unsigned g_xa[8 * 8 * 128 * 8];            // 256KB
// Packed W images (prep_w writes): per (node i, tile t) a 32KB image,
// byte[k*256 + ((n*2) ^ ((k&7)<<4))] = fp16(W[k][n]) — exactly the smem
// layout the main kernel's LDM4T addressing expects.
__device__ __align__(16) unsigned g_pbh[(size_t)N_ * NT * 8192];    // 37.7MB

// ---------------- helpers ----------------
__device__ __forceinline__ uint32_t smem_u32(const void* p) {
    uint32_t a;
    asm("{ .reg .u64 t; cvta.to.shared.u64 t, %1; cvt.u32.u64 %0, t; }" : "=r"(a) : "l"(p));
    return a;
}
__device__ __forceinline__ unsigned pack_h2(float f0, float f1) {
    __half2 t = __floats2half2_rn(f0, f1);
    return *reinterpret_cast<unsigned*>(&t);
}
__device__ __forceinline__ float elu1(float x) {
    return x > 0.0f ? x : (__expf(x) - 1.0f);
}
__device__ __forceinline__ float ex2(float x) {
    float r;
    asm("ex2.approx.ftz.f32 %0, %1;" : "=f"(r) : "f"(x));
    return r;
}

#define CP16(s, g) asm volatile("cp.async.cg.shared.global [%0], [%1], 16;" :: "r"(s), "l"(g))
#define CP_COMMIT() asm volatile("cp.async.commit_group;" ::: "memory")
#define CP_WAIT(n)  asm volatile("cp.async.wait_group %0;" :: "n"(n) : "memory")

#define LDM4(r0, r1, r2, r3, a) \
    asm volatile("ldmatrix.sync.aligned.m8n8.x4.shared.b16 {%0,%1,%2,%3}, [%4];" \
        : "=r"(r0), "=r"(r1), "=r"(r2), "=r"(r3) : "r"(a))

#define LDM4T(r0, r1, r2, r3, a) \
    asm volatile("ldmatrix.sync.aligned.m8n8.x4.trans.shared.b16 {%0,%1,%2,%3}, [%4];" \
        : "=r"(r0), "=r"(r1), "=r"(r2), "=r"(r3) : "r"(a))

#define MMA16816(c, a, b) \
    asm volatile("mma.sync.aligned.m16n8k16.row.col.f32.f16.f16.f32 " \
        "{%0,%1,%2,%3}, {%4,%5,%6,%7}, {%8,%9}, {%0,%1,%2,%3};" \
        : "+f"((c)[0]), "+f"((c)[1]), "+f"((c)[2]), "+f"((c)[3]) \
        : "r"((a)[0]), "r"((a)[1]), "r"((a)[2]), "r"((a)[3]), "r"((b)[0]), "r"((b)[1]))

#define ZACC(q, zaddr) \
    asm volatile("ld.shared.v4.f32 {%0,%1,%2,%3}, [%4];" \
        : "=f"((q)[0]), "=f"((q)[1]), "=f"((q)[2]), "=f"((q)[3]) : "r"(zaddr))

// ---------------- prep: x -> g_xa (fp16, pre-scaled by log2e) ----------------
__global__ void prep_x(const float* __restrict__ x) {
    int idx = blockIdx.x * blockDim.x + threadIdx.x;       // one u32 each
    if (idx >= 65536) return;
    int mt = idx >> 13;             // 8192 u32 per m-tile
    int c  = (idx >> 10) & 7;       // chunk 0..7
    int m  = (idx >> 3) & 127;
    int p  = idx & 7;
    int row = mt * 128 + m;
    int kb = c * 16 + 2 * p;
    g_xa[idx] = pack_h2(x[row * 128 + kb] * LOG2E, x[row * 128 + kb + 1] * LOG2E);
}

// ---------------- prep: weights -> swizzled fp16 images (g_pbh) --------------
// grid (9, 128), 256 threads. Reads coalesced fp32 rows, writes the exact
// [k][n] swizzled layout consumed by the main kernel's ldmatrix.trans.
__global__ void prep_w(const float* __restrict__ fw, const float* __restrict__ gw) {
    const int t = blockIdx.x, i = blockIdx.y;
    const int l = threadIdx.x & 31, w = threadIdx.x >> 5;   // warp = k mod 8
    const float* src;
    int stride;
    if (t < 8) { src = gw + (size_t)i * 131072 + t * 128; stride = 1024; }
    else       { src = fw + (size_t)i * 16384;            stride = 128; }
    char* out = (char*)g_pbh + (size_t)(i * NT + t) * 32768;
    const uint32_t swb = (uint32_t)((l * 8) ^ (w << 4));
#pragma unroll
    for (int j = 0; j < 16; ++j) {
        int k = j * 8 + w;
        float4 v = *reinterpret_cast<const float4*>(src + (size_t)k * stride + l * 4);
        uint2 h;
        h.x = pack_h2(v.x, v.y);
        h.y = pack_h2(v.z, v.w);
        *reinterpret_cast<uint2*>(out + k * 256 + swb) = h;
    }
}

// ---------------- main fused kernel ----------------
// grid (8 m-tiles, 128 nodes), 256 threads = 8 warps, 2 CTAs/SM.
// Warp tile 32x64 as two 32x32 n-halves; A/B fragments double-buffered;
// B tiles cp.async'd from pre-swizzled fp16 images (double-buffered smem).
// smem: B0 32KB | B1 32KB | XA 32KB | Wg 512B | Wf 512B | Z 32B
#define SM_B0 0
#define SM_B1 32768
#define SM_XA 65536
#define SM_WG 98304
#define SM_WF 98816
#define SM_Z  99328
#define SM_TOT 99360

__global__ __launch_bounds__(256, 2)
void sde_main(const float* __restrict__ Wf, const float* __restrict__ bfv,
              const float* __restrict__ Wg, const float* __restrict__ bgv,
              float* __restrict__ fout, float* __restrict__ gout) {
    extern __shared__ char smem[];
    const uint32_t sb = smem_u32(smem);
    const int tid = threadIdx.x, l = tid & 31, wid = tid >> 5;
    const int i = blockIdx.y, b0 = blockIdx.x * 128;
    const int warp_m = (wid & 3) * 32;
    const int warp_n = (wid >> 2) * 64;
    float* Wg_s = (float*)(smem + SM_WG);
    float* Wf_s = (float*)(smem + SM_WF);
    const uint32_t zaddr = sb + SM_Z;

    const char* asrc = (const char*)g_xa + (size_t)blockIdx.x * 32768;
    const char* bsrc = (const char*)g_pbh + (size_t)(i * NT) * 32768;

    // group 0: XA + B tile 0
#pragma unroll
    for (int j = 0; j < 8; ++j) {
        uint32_t off = (uint32_t)(j * 256 + tid) * 16;
        CP16(sb + SM_XA + off, asrc + off);
        CP16(sb + SM_B0 + off, bsrc + off);
    }
    CP_COMMIT();
    // group 1: B tile 1
#pragma unroll
    for (int j = 0; j < 8; ++j) {
        uint32_t off = (uint32_t)(j * 256 + tid) * 16;
        CP16(sb + SM_B1 + off, bsrc + 32768 + off);
    }
    CP_COMMIT();

    if (tid < 128) { Wg_s[tid] = Wg[i * H_ + tid]; Wf_s[tid] = Wf[i * H_ + tid]; }
    if (tid < 4) ((float*)(smem + SM_Z))[tid] = 0.0f;
    CP_WAIT(1);          // group 0 (XA + tile 0) complete
    __syncthreads();

    // sumWg = sum_h Wg[i,h]  (folded "-1" elu term)
    if (wid == 0) {
        float sv = Wg_s[l] + Wg_s[l + 32] + Wg_s[l + 64] + Wg_s[l + 96];
#pragma unroll
        for (int o = 16; o; o >>= 1) sv += __shfl_xor_sync(0xffffffffu, sv, o);
        if (l == 0) *(float*)(smem + SM_Z + 16) = sv;
    }
    __syncthreads();

    // fragment addressing constants
    const uint32_t aoff = (uint32_t)((warp_m + (l & 15)) * 32 + (l >> 4) * 16);
    const int kl   = (l & 7) + ((l >> 4) << 3);
    const int jofs = (l >> 3) & 1;
    const int swl  = (l & 7) << 4;

#define LDA2(dst, s_) do { \
        _Pragma("unroll") \
        for (int im_ = 0; im_ < 2; ++im_) \
            LDM4((dst)[im_][0], (dst)[im_][1], (dst)[im_][2], (dst)[im_][3], \
                 sb + SM_XA + (uint32_t)((s_) * 4096) + aoff + im_ * 512); \
    } while (0)
#define LDB2(dst, bufoff_, nb_, s_) do { \
        uint32_t kk_ = (uint32_t)((s_) * 16 + kl); \
        _Pragma("unroll") \
        for (int p_ = 0; p_ < 2; ++p_) { \
            uint32_t roff_ = (uint32_t)((((nb_) + p_ * 16 + jofs * 8) * 2) ^ swl); \
            LDM4T((dst)[2 * p_][0], (dst)[2 * p_ + 1][0], \
                  (dst)[2 * p_][1], (dst)[2 * p_ + 1][1], \
                  sb + (uint32_t)(bufoff_) + kk_ * 256 + roff_); \
        } \
    } while (0)

    float accg[4][2], accf[4];
#pragma unroll
    for (int r = 0; r < 4; ++r) {
        accg[r][0] = 0.f; accg[r][1] = 0.f; accf[r] = 0.f;
    }

    for (int t = 0; t < NT; ++t) {
        const uint32_t bbase = (uint32_t)((t & 1) ? SM_B1 : SM_B0);

        uint32_t af[2][2][4], bfr[2][4][2];
        LDA2(af[0], 0);
        LDB2(bfr[0], bbase, warp_n, 0);

#pragma unroll
        for (int half = 0; half < 2; ++half) {
            const int nb = warp_n + half * 32;
            float acc[4][2][4];
#pragma unroll
            for (int in = 0; in < 4; ++in)
#pragma unroll
                for (int im = 0; im < 2; ++im)
                    ZACC(acc[in][im], zaddr);

#pragma unroll
            for (int s = 0; s < 8; ++s) {
                if (s < 7) {
                    LDA2(af[(s + 1) & 1], s + 1);
                    LDB2(bfr[(s + 1) & 1], bbase, nb, s + 1);
                } else if (half == 0) {
                    LDA2(af[0], 0);
                    LDB2(bfr[0], bbase, warp_n + 32, 0);
                }
#pragma unroll
                for (int im = 0; im < 2; ++im)
#pragma unroll
                    for (int in = 0; in < 4; ++in)
                        MMA16816(acc[in][im], af[s & 1][im], bfr[s & 1][in]);
            }

            // fused epilogue for this 32-col half — acc holds x' = log2e*temp
            if (t < 8) {
                const int hb = t * 16 + (wid >> 2) * 8 + half * 4;
#pragma unroll
                for (int in = 0; in < 4; ++in) {
                    const float w = Wg_s[hb + in];
#pragma unroll
                    for (int im = 0; im < 2; ++im) {
#pragma unroll
                        for (int r = 0; r < 4; ++r) {
                            float v = acc[in][im][r];
                            float mx = fmaxf(v, 0.0f);
                            float e  = ex2(fminf(v, 0.0f));
                            const int slot = im * 2 + (r >> 1), pcol = r & 1;
                            accg[slot][pcol] =
                                fmaf(w, fmaf(mx, LN2, e), accg[slot][pcol]);
                        }
                    }
                }
            } else {
                const int cb = nb + 2 * (l & 3);
#pragma unroll
                for (int in = 0; in < 4; ++in) {
                    const float w0 = Wf_s[cb + in * 8], w1 = Wf_s[cb + in * 8 + 1];
#pragma unroll
                    for (int im = 0; im < 2; ++im) {
                        accf[im * 2]     += w0 * elu1(acc[in][im][0] * LN2) +
                                            w1 * elu1(acc[in][im][1] * LN2);
                        accf[im * 2 + 1] += w0 * elu1(acc[in][im][2] * LN2) +
                                            w1 * elu1(acc[in][im][3] * LN2);
                    }
                }
            }
        }

        __syncthreads();             // all warps done reading bbase
        if (t + 2 < NT) {            // prefetch tile t+2 into the freed buffer
            const char* src = bsrc + (size_t)(t + 2) * 32768;
#pragma unroll
            for (int j = 0; j < 8; ++j) {
                uint32_t off = (uint32_t)(j * 256 + tid) * 16;
                CP16(sb + bbase + off, src + off);
            }
            CP_COMMIT();
            CP_WAIT(1);              // tile t+1 group complete
            __syncthreads();
        } else if (t + 1 < NT) {
            CP_WAIT(0);              // last pending group (tile t+1)
            __syncthreads();
        }
    }

    // cross-warp reduction: n-warps 4-7 hand partials to warps 0-3
    float* red = (float*)smem;                 // reuse B region (Z untouched)
    const int base = ((wid & 3) * 32 + l) * 12;
    if (wid >= 4) {
#pragma unroll
        for (int r = 0; r < 4; ++r) {
            red[base + r * 2]     = accg[r][0];
            red[base + r * 2 + 1] = accg[r][1];
            red[base + 8 + r]     = accf[r];
        }
    }
    __syncthreads();
    if (wid < 4) {
        const float bgi = bgv[i], bfi = bfv[i];
        const float sumWg = *(const float*)(smem + SM_Z + 16);
#pragma unroll
        for (int r = 0; r < 4; ++r) {
            float g0 = accg[r][0] + red[base + r * 2]     - sumWg;
            float g1 = accg[r][1] + red[base + r * 2 + 1] - sumWg;
            float vf = accf[r] + red[base + 8 + r];
            const int row = b0 + warp_m + (r >> 1) * 16 + (r & 1) * 8 + (l >> 2);
            *reinterpret_cast<float2*>(gout + ((size_t)row * 128 + i) * 8 + 2 * (l & 3)) =
                make_float2(g0 + bgi, g1 + bgi);
            vf += __shfl_xor_sync(0xffffffffu, vf, 1);
            vf += __shfl_xor_sync(0xffffffffu, vf, 2);
            if ((l & 3) == 0) fout[(size_t)row * 128 + i] = vf + bfi;
        }
    }
}

// ---------------- launch ----------------
extern "C" void kernel_launch(void* const* d_in, const int* in_sizes, int n_in,
                              void* d_out, int out_size) {
    (void)in_sizes; (void)n_in; (void)out_size;
    const float* x  = (const float*)d_in[0];
    const float* fw = (const float*)d_in[1];
    const float* gw = (const float*)d_in[2];
    const float* Wf = (const float*)d_in[3];
    const float* bf = (const float*)d_in[4];
    const float* Wg = (const float*)d_in[5];
    const float* bg = (const float*)d_in[6];
    float* out  = (float*)d_out;
    float* fout = out;                      // [B,N]
    float* gout = out + (size_t)B_ * N_;    // [B,N,D]

    static bool attr_set = false;
    if (!attr_set) {
        cudaFuncSetAttribute(sde_main, cudaFuncAttributeMaxDynamicSharedMemorySize, SM_TOT);
        attr_set = true;
    }

    prep_x<<<256, 256>>>(x);
    prep_w<<<dim3(NT, N_), 256>>>(fw, gw);
    sde_main<<<dim3(8, N_), 256, SM_TOT>>>(Wf, bf, Wg, bg, fout, gout);
}